// round 2
// baseline (speedup 1.0000x reference)
#include <cuda_runtime.h>

#define HDIM 128
#define BE 64          // rows (edges/nodes) per block tile
#define KC 32          // K chunk staged through smem
#define NTHREADS 256
#define MAX_NODES 50000

// scatter-add destination for edge messages: [N, H]
__device__ float g_agg[(size_t)MAX_NODES * HDIM];

// dynamic smem layout (floats):
//   Bsm : KC * HDIM                (W chunk)
//   Asm : BE * (KC+1)              (gathered input chunk, padded)
//   Hsm : BE * (HDIM+4)            (hidden activations, padded)
//   sidx: 2*BE ints                (row/col indices, edge mode)
#define SMEM_FLOATS (KC*HDIM + BE*(KC+1) + BE*(HDIM+4))
#define SMEM_BYTES  (SMEM_FLOATS*4 + BE*2*4)

// MODE 0: edge MLP  (gather x[row]||x[col]||edge_attr, K1=384, scatter-add to g_agg)
// MODE 1: node MLP  (gather x||agg, K1=256, store to out)
template<int MODE>
__global__ __launch_bounds__(NTHREADS, 2)
void gnn_mlp_kernel(const float* __restrict__ x,
                    const int* __restrict__ ei,     // int32 [2, E]
                    const float* __restrict__ eattr,
                    const float* __restrict__ W1, const float* __restrict__ b1,
                    const float* __restrict__ W2, const float* __restrict__ b2,
                    float* __restrict__ out,
                    int nrows, int K1, int E)
{
    extern __shared__ float sm[];
    float* Bsm = sm;                          // [KC][HDIM]
    float* Asm = Bsm + KC*HDIM;               // [BE][KC+1]
    float* Hsm = Asm + BE*(KC+1);             // [BE][HDIM+4]
    int*   sidx = (int*)(Hsm + BE*(HDIM+4));  // [2][BE]  (row, col)

    const int tid  = threadIdx.x;
    const int base = blockIdx.x * BE;

    if (MODE == 0) {
        if (tid < BE) {
            int e = base + tid; if (e >= nrows) e = nrows - 1;
            sidx[tid]      = ei[e];              // row (source)
            sidx[BE + tid] = ei[E + e];          // col (dest)
        }
        __syncthreads();
    }

    const int tcol = tid & 31;       // 32 col-groups of 4
    const int trow = tid >> 5;       // 8 row-groups of 8
    const int j0 = tcol * 4;
    const int e0 = trow * 8;

    // A-load assignment: thread covers 8 consecutive k for one row
    const int le = tid >> 2;                   // 0..63 row within tile
    const int lq = tid & 3;                    // which 8-k slice of the 32-chunk
    const int lr = (base + le < nrows) ? (base + le) : (nrows - 1);

    // B-load assignment: thread covers 16 consecutive cols of one k-row
    const int bk = tid >> 3;                   // 0..31
    const int bj = (tid & 7) * 16;

    float acc[8][4];
    #pragma unroll
    for (int i = 0; i < 8; i++) {
        #pragma unroll
        for (int j = 0; j < 4; j++) acc[i][j] = b1[j0 + j];
    }

    // ================= GEMM1: [BE, K1] @ W1[K1, H] =================
    for (int kc = 0; kc < K1; kc += KC) {
        // ---- stage gathered A chunk ----
        {
            int kg = kc + lq * 8;
            const float* src;
            if (MODE == 0) {
                if (kg < HDIM)          src = x     + (size_t)sidx[le]      * HDIM + kg;
                else if (kg < 2*HDIM)   src = x     + (size_t)sidx[BE + le] * HDIM + (kg - HDIM);
                else                    src = eattr + (size_t)lr            * HDIM + (kg - 2*HDIM);
            } else {
                if (kg < HDIM)          src = x     + (size_t)lr * HDIM + kg;
                else                    src = g_agg + (size_t)lr * HDIM + (kg - HDIM);
            }
            float4 v0 = ((const float4*)src)[0];
            float4 v1 = ((const float4*)src)[1];
            float* dst = Asm + le*(KC+1) + lq*8;
            dst[0]=v0.x; dst[1]=v0.y; dst[2]=v0.z; dst[3]=v0.w;
            dst[4]=v1.x; dst[5]=v1.y; dst[6]=v1.z; dst[7]=v1.w;
        }
        // ---- stage W1 chunk ----
        {
            const float4* s = (const float4*)(W1 + (size_t)(kc + bk)*HDIM + bj);
            float4*       d = (float4*)(Bsm + bk*HDIM + bj);
            d[0]=s[0]; d[1]=s[1]; d[2]=s[2]; d[3]=s[3];
        }
        __syncthreads();
        #pragma unroll
        for (int kk = 0; kk < KC; ++kk) {
            float4 b = *(const float4*)(Bsm + kk*HDIM + j0);
            float a[8];
            #pragma unroll
            for (int i = 0; i < 8; i++) a[i] = Asm[(e0+i)*(KC+1) + kk];
            #pragma unroll
            for (int i = 0; i < 8; i++) {
                acc[i][0] += a[i]*b.x; acc[i][1] += a[i]*b.y;
                acc[i][2] += a[i]*b.z; acc[i][3] += a[i]*b.w;
            }
        }
        __syncthreads();
    }

    // ================= hidden: ReLU -> Hsm =================
    #pragma unroll
    for (int i = 0; i < 8; i++) {
        float4 h;
        h.x = fmaxf(acc[i][0], 0.f); h.y = fmaxf(acc[i][1], 0.f);
        h.z = fmaxf(acc[i][2], 0.f); h.w = fmaxf(acc[i][3], 0.f);
        *(float4*)(Hsm + (e0+i)*(HDIM+4) + j0) = h;
    }

    #pragma unroll
    for (int i = 0; i < 8; i++) {
        #pragma unroll
        for (int j = 0; j < 4; j++) acc[i][j] = b2[j0 + j];
    }

    // ================= GEMM2: Hsm[BE, H] @ W2[H, H] =================
    for (int kc = 0; kc < HDIM; kc += KC) {
        {
            const float4* s = (const float4*)(W2 + (size_t)(kc + bk)*HDIM + bj);
            float4*       d = (float4*)(Bsm + bk*HDIM + bj);
            d[0]=s[0]; d[1]=s[1]; d[2]=s[2]; d[3]=s[3];
        }
        __syncthreads();   // also orders Hsm stores before reads
        #pragma unroll
        for (int kk = 0; kk < KC; ++kk) {
            float4 b = *(const float4*)(Bsm + kk*HDIM + j0);
            float a[8];
            #pragma unroll
            for (int i = 0; i < 8; i++) a[i] = Hsm[(e0+i)*(HDIM+4) + kc + kk];
            #pragma unroll
            for (int i = 0; i < 8; i++) {
                acc[i][0] += a[i]*b.x; acc[i][1] += a[i]*b.y;
                acc[i][2] += a[i]*b.z; acc[i][3] += a[i]*b.w;
            }
        }
        __syncthreads();
    }

    // ================= epilogue =================
    if (MODE == 0) {
        #pragma unroll
        for (int i = 0; i < 8; i++) {
            int e = base + e0 + i;
            if (e < nrows) {
                int c = sidx[BE + e0 + i];
                float* dst = g_agg + (size_t)c * HDIM + j0;
                atomicAdd(dst+0, acc[i][0]);
                atomicAdd(dst+1, acc[i][1]);
                atomicAdd(dst+2, acc[i][2]);
                atomicAdd(dst+3, acc[i][3]);
            }
        }
    } else {
        #pragma unroll
        for (int i = 0; i < 8; i++) {
            int r = base + e0 + i;
            if (r < nrows) {
                float4 v;
                v.x = acc[i][0]; v.y = acc[i][1]; v.z = acc[i][2]; v.w = acc[i][3];
                *(float4*)(out + (size_t)r * HDIM + j0) = v;
            }
        }
    }
}

extern "C" void kernel_launch(void* const* d_in, const int* in_sizes, int n_in,
                              void* d_out, int out_size)
{
    const float* x     = (const float*)d_in[0];
    const int*   ei    = (const int*)d_in[1];    // int32 [2, E] (JAX x64 disabled)
    const float* eattr = (const float*)d_in[2];
    const float* We1   = (const float*)d_in[3];
    const float* be1   = (const float*)d_in[4];
    const float* We2   = (const float*)d_in[5];
    const float* be2   = (const float*)d_in[6];
    const float* Wn1   = (const float*)d_in[7];
    const float* bn1   = (const float*)d_in[8];
    const float* Wn2   = (const float*)d_in[9];
    const float* bn2   = (const float*)d_in[10];
    float* out = (float*)d_out;

    const int N = in_sizes[0] / HDIM;   // 50000
    const int E = in_sizes[2] / HDIM;   // 800000

    cudaFuncSetAttribute(gnn_mlp_kernel<0>,
                         cudaFuncAttributeMaxDynamicSharedMemorySize, SMEM_BYTES);
    cudaFuncSetAttribute(gnn_mlp_kernel<1>,
                         cudaFuncAttributeMaxDynamicSharedMemorySize, SMEM_BYTES);

    void* aggp = nullptr;
    cudaGetSymbolAddress(&aggp, g_agg);
    cudaMemsetAsync(aggp, 0, (size_t)N * HDIM * sizeof(float), 0);

    const int gridE = (E + BE - 1) / BE;
    gnn_mlp_kernel<0><<<gridE, NTHREADS, SMEM_BYTES>>>(
        x, ei, eattr, We1, be1, We2, be2, nullptr, E, 3*HDIM, E);

    const int gridN = (N + BE - 1) / BE;
    gnn_mlp_kernel<1><<<gridN, NTHREADS, SMEM_BYTES>>>(
        x, nullptr, nullptr, Wn1, bn1, Wn2, bn2, out, N, 2*HDIM, 0);
}

// round 4
// speedup vs baseline: 2.6027x; 2.6027x over previous
#include <cuda_runtime.h>
#include <cstdint>

#define HDIM 128
#define MAX_NODES 50000

// ---------------- device scratch ----------------
__device__ float g_agg[(size_t)MAX_NODES * HDIM];
__device__ float g_W1T[HDIM * 384];     // edge W1^T [n][k], tf32-rounded
__device__ float g_W2T[HDIM * HDIM];
__device__ float g_Wn1T[HDIM * 256];
__device__ float g_Wn2T[HDIM * HDIM];

__device__ __forceinline__ float to_tf32(float x) {
    float y; asm("cvt.rna.tf32.f32 %0, %1;" : "=f"(y) : "f"(x)); return y;
}

__device__ __forceinline__ void mma_tf32(float c[4],
    uint32_t a0, uint32_t a1, uint32_t a2, uint32_t a3,
    uint32_t b0, uint32_t b1)
{
    asm volatile("mma.sync.aligned.m16n8k8.row.col.f32.tf32.tf32.f32 "
        "{%0,%1,%2,%3},{%4,%5,%6,%7},{%8,%9},{%0,%1,%2,%3};"
        : "+f"(c[0]), "+f"(c[1]), "+f"(c[2]), "+f"(c[3])
        : "r"(a0), "r"(a1), "r"(a2), "r"(a3), "r"(b0), "r"(b1));
}

// ---- smem layout in float slots ----
// Asm [128][36], Bsm [128][36], Hsm [128][132], sidx 256 ints, b1s/b2s 128 each
#define A_F   0
#define B_F   4608
#define H_F   9216
#define IDX_F 26112
#define B1_F  26368
#define B2_F  26496
#define SMEM_BYTES (26624 * 4)   // 106496 B -> 2 CTAs/SM

// MODE 0: edge MLP (gather x[src]||x[dst]||eattr, K1=384, red-scatter to g_agg)
// MODE 1: node MLP (gather x||agg, K1=256, store to out)
template <int MODE, int K1>
__global__ __launch_bounds__(256, 2)
void gnn_mma_kernel(const float* __restrict__ x,
                    const int* __restrict__ ei,
                    const float* __restrict__ eattr,
                    const float* __restrict__ W1T, const float* __restrict__ b1,
                    const float* __restrict__ W2T, const float* __restrict__ b2,
                    float* __restrict__ out, int nrows, int E)
{
    extern __shared__ float sm[];
    float* Asm = sm + A_F;
    float* Bsm = sm + B_F;
    float* Hsm = sm + H_F;
    int*   sidx = (int*)(sm + IDX_F);
    float* b1s = sm + B1_F;
    float* b2s = sm + B2_F;

    const int tid = threadIdx.x, lane = tid & 31, wid = tid >> 5;
    const int base = blockIdx.x * 128;
    const int wm = wid >> 1, wn = wid & 1;       // warp grid 4x2
    const int g = lane >> 2, q = lane & 3;       // mma lane coords

    if (tid < 128) {
        b1s[tid] = b1[tid];
        b2s[tid] = b2[tid];
        if (MODE == 0) {
            int e = base + tid; if (e >= nrows) e = nrows - 1;
            sidx[tid]       = ei[e];       // src
            sidx[128 + tid] = ei[E + e];   // dst
        }
    }
    __syncthreads();

    // loader: thread -> row le, 16-float half h
    const int le = tid >> 1;
    const int h  = tid & 1;
    int lr = base + le; if (lr >= nrows) lr = nrows - 1;

    // ---------------- accumulators, bias-initialized (b1) ----------------
    float acc[2][8][4];
    #pragma unroll
    for (int mt = 0; mt < 2; ++mt)
        #pragma unroll
        for (int nt = 0; nt < 8; ++nt) {
            const int n = wn * 64 + nt * 8 + q * 2;
            acc[mt][nt][0] = b1s[n];     acc[mt][nt][1] = b1s[n + 1];
            acc[mt][nt][2] = b1s[n];     acc[mt][nt][3] = b1s[n + 1];
        }

    // ================= GEMM1: [128,K1] @ W1T^T -> acc =================
    #pragma unroll 1
    for (int c = 0; c < K1 / 32; ++c) {
        {   // gathered A chunk (tf32-round at store)
            const int g0 = c * 32 + h * 16;
            const float* src;
            if (MODE == 0) {
                if (g0 < 128)      src = x + (size_t)sidx[le] * HDIM + g0;
                else if (g0 < 256) src = x + (size_t)sidx[128 + le] * HDIM + (g0 - 128);
                else               src = eattr + (size_t)lr * HDIM + (g0 - 256);
            } else {
                if (g0 < 128)      src = x + (size_t)lr * HDIM + g0;
                else               src = g_agg + (size_t)lr * HDIM + (g0 - 128);
            }
            float* dst = Asm + le * 36 + h * 16;
            #pragma unroll
            for (int i = 0; i < 4; ++i) {
                float4 v = ((const float4*)src)[i];
                dst[i*4+0] = to_tf32(v.x); dst[i*4+1] = to_tf32(v.y);
                dst[i*4+2] = to_tf32(v.z); dst[i*4+3] = to_tf32(v.w);
            }
        }
        {   // weight chunk (pre-rounded)
            const float* src = W1T + (size_t)le * K1 + c * 32 + h * 16;
            float* dst = Bsm + le * 36 + h * 16;
            #pragma unroll
            for (int i = 0; i < 4; ++i)
                ((float4*)dst)[i] = ((const float4*)src)[i];
        }
        __syncthreads();
        #pragma unroll
        for (int ks = 0; ks < 4; ++ks) {
            const int k0 = ks * 8;
            uint32_t a[2][4];
            #pragma unroll
            for (int mt = 0; mt < 2; ++mt) {
                const int r0 = wm * 32 + mt * 16 + g;
                a[mt][0] = __float_as_uint(Asm[r0 * 36 + k0 + q]);
                a[mt][1] = __float_as_uint(Asm[(r0 + 8) * 36 + k0 + q]);
                a[mt][2] = __float_as_uint(Asm[r0 * 36 + k0 + 4 + q]);
                a[mt][3] = __float_as_uint(Asm[(r0 + 8) * 36 + k0 + 4 + q]);
            }
            #pragma unroll
            for (int nt = 0; nt < 8; ++nt) {
                const int nr = wn * 64 + nt * 8 + g;
                uint32_t b0 = __float_as_uint(Bsm[nr * 36 + k0 + q]);
                uint32_t bb = __float_as_uint(Bsm[nr * 36 + k0 + 4 + q]);
                mma_tf32(acc[0][nt], a[0][0], a[0][1], a[0][2], a[0][3], b0, bb);
                mma_tf32(acc[1][nt], a[1][0], a[1][1], a[1][2], a[1][3], b0, bb);
            }
        }
        __syncthreads();
    }

    // ================= hidden: ReLU -> tf32 -> Hsm =================
    #pragma unroll
    for (int mt = 0; mt < 2; ++mt)
        #pragma unroll
        for (int nt = 0; nt < 8; ++nt) {
            const int m = wm * 32 + mt * 16 + g;
            const int n = wn * 64 + nt * 8 + q * 2;
            float2 lo, hi;
            lo.x = to_tf32(fmaxf(acc[mt][nt][0], 0.f));
            lo.y = to_tf32(fmaxf(acc[mt][nt][1], 0.f));
            hi.x = to_tf32(fmaxf(acc[mt][nt][2], 0.f));
            hi.y = to_tf32(fmaxf(acc[mt][nt][3], 0.f));
            *(float2*)(Hsm + m * 132 + n)       = lo;
            *(float2*)(Hsm + (m + 8) * 132 + n) = hi;
        }

    // re-init accumulators with b2
    #pragma unroll
    for (int mt = 0; mt < 2; ++mt)
        #pragma unroll
        for (int nt = 0; nt < 8; ++nt) {
            const int n = wn * 64 + nt * 8 + q * 2;
            acc[mt][nt][0] = b2s[n];     acc[mt][nt][1] = b2s[n + 1];
            acc[mt][nt][2] = b2s[n];     acc[mt][nt][3] = b2s[n + 1];
        }
    __syncthreads();

    // ================= GEMM2: Hsm[128,128] @ W2T^T -> acc =================
    #pragma unroll 1
    for (int c = 0; c < 4; ++c) {
        {
            const float* src = W2T + (size_t)le * HDIM + c * 32 + h * 16;
            float* dst = Bsm + le * 36 + h * 16;
            #pragma unroll
            for (int i = 0; i < 4; ++i)
                ((float4*)dst)[i] = ((const float4*)src)[i];
        }
        __syncthreads();
        #pragma unroll
        for (int ks = 0; ks < 4; ++ks) {
            const int k0 = c * 32 + ks * 8;
            uint32_t a[2][4];
            #pragma unroll
            for (int mt = 0; mt < 2; ++mt) {
                const int r0 = wm * 32 + mt * 16 + g;
                a[mt][0] = __float_as_uint(Hsm[r0 * 132 + k0 + q]);
                a[mt][1] = __float_as_uint(Hsm[(r0 + 8) * 132 + k0 + q]);
                a[mt][2] = __float_as_uint(Hsm[r0 * 132 + k0 + 4 + q]);
                a[mt][3] = __float_as_uint(Hsm[(r0 + 8) * 132 + k0 + 4 + q]);
            }
            #pragma unroll
            for (int nt = 0; nt < 8; ++nt) {
                const int nr = wn * 64 + nt * 8 + g;
                uint32_t b0 = __float_as_uint(Bsm[nr * 36 + (ks*8) + q]);
                uint32_t bb = __float_as_uint(Bsm[nr * 36 + (ks*8) + 4 + q]);
                mma_tf32(acc[0][nt], a[0][0], a[0][1], a[0][2], a[0][3], b0, bb);
                mma_tf32(acc[1][nt], a[1][0], a[1][1], a[1][2], a[1][3], b0, bb);
            }
        }
        __syncthreads();
    }

    // ================= epilogue: stage to Hsm, scatter / store ============
    #pragma unroll
    for (int mt = 0; mt < 2; ++mt)
        #pragma unroll
        for (int nt = 0; nt < 8; ++nt) {
            const int m = wm * 32 + mt * 16 + g;
            const int n = wn * 64 + nt * 8 + q * 2;
            float2 lo, hi;
            lo.x = acc[mt][nt][0]; lo.y = acc[mt][nt][1];
            hi.x = acc[mt][nt][2]; hi.y = acc[mt][nt][3];
            *(float2*)(Hsm + m * 132 + n)       = lo;
            *(float2*)(Hsm + (m + 8) * 132 + n) = hi;
        }
    __syncthreads();

    {
        const int row = tid >> 1;
        const int hh  = tid & 1;
        if (base + row < nrows) {
            const float* s = Hsm + row * 132 + hh * 64;
            if (MODE == 0) {
                const int cd = sidx[128 + row];
                float* dst = g_agg + (size_t)cd * HDIM + hh * 64;
                #pragma unroll
                for (int i = 0; i < 16; ++i) {
                    float4 v = ((const float4*)s)[i];
                    asm volatile("red.global.add.v4.f32 [%0], {%1,%2,%3,%4};"
                                 :: "l"(dst + i * 4), "f"(v.x), "f"(v.y),
                                    "f"(v.z), "f"(v.w) : "memory");
                }
            } else {
                float4* dst = (float4*)(out + (size_t)(base + row) * HDIM + hh * 64);
                #pragma unroll
                for (int i = 0; i < 16; ++i)
                    dst[i] = ((const float4*)s)[i];
            }
        }
    }
}

// transpose + tf32-round: dst[n*K+k] = tf32(src[k*N+n]), N==128
__global__ void prep_wT(float* dst, const float* src, int K) {
    int i = blockIdx.x * 256 + threadIdx.x;
    if (i < K * HDIM) {
        int k = i / HDIM, n = i % HDIM;
        dst[(size_t)n * K + k] = to_tf32(src[(size_t)k * HDIM + n]);
    }
}

extern "C" void kernel_launch(void* const* d_in, const int* in_sizes, int n_in,
                              void* d_out, int out_size)
{
    const float* x     = (const float*)d_in[0];
    const int*   ei    = (const int*)d_in[1];
    const float* eattr = (const float*)d_in[2];
    const float* We1   = (const float*)d_in[3];
    const float* be1   = (const float*)d_in[4];
    const float* We2   = (const float*)d_in[5];
    const float* be2   = (const float*)d_in[6];
    const float* Wn1   = (const float*)d_in[7];
    const float* bn1   = (const float*)d_in[8];
    const float* Wn2   = (const float*)d_in[9];
    const float* bn2   = (const float*)d_in[10];
    float* out = (float*)d_out;

    const int N = in_sizes[0] / HDIM;   // 50000
    const int E = in_sizes[1] / 2;      // 800000

    cudaFuncSetAttribute(gnn_mma_kernel<0, 384>,
                         cudaFuncAttributeMaxDynamicSharedMemorySize, SMEM_BYTES);
    cudaFuncSetAttribute(gnn_mma_kernel<1, 256>,
                         cudaFuncAttributeMaxDynamicSharedMemorySize, SMEM_BYTES);

    void *aggp, *w1t, *w2t, *wn1t, *wn2t;
    cudaGetSymbolAddress(&aggp, g_agg);
    cudaGetSymbolAddress(&w1t,  g_W1T);
    cudaGetSymbolAddress(&w2t,  g_W2T);
    cudaGetSymbolAddress(&wn1t, g_Wn1T);
    cudaGetSymbolAddress(&wn2t, g_Wn2T);

    cudaMemsetAsync(aggp, 0, (size_t)N * HDIM * sizeof(float), 0);
    prep_wT<<<(384 * HDIM + 255) / 256, 256>>>((float*)w1t,  We1, 384);
    prep_wT<<<(HDIM * HDIM + 255) / 256, 256>>>((float*)w2t,  We2, HDIM);
    prep_wT<<<(256 * HDIM + 255) / 256, 256>>>((float*)wn1t, Wn1, 256);
    prep_wT<<<(HDIM * HDIM + 255) / 256, 256>>>((float*)wn2t, Wn2, HDIM);

    gnn_mma_kernel<0, 384><<<(E + 127) / 128, 256, SMEM_BYTES>>>(
        x, ei, eattr, (const float*)w1t, be1, (const float*)w2t, be2,
        nullptr, E, E);
    gnn_mma_kernel<1, 256><<<(N + 127) / 128, 256, SMEM_BYTES>>>(
        x, nullptr, nullptr, (const float*)wn1t, bn1, (const float*)wn2t, bn2,
        out, N, 0);
}

// round 6
// speedup vs baseline: 4.5438x; 1.7458x over previous
#include <cuda_runtime.h>
#include <cuda_fp16.h>
#include <cstdint>

#define HDIM 128
#define MAX_NODES 50000
#define MAX_EDGES 800000

// ---------------- device scratch ----------------
__device__ float  g_agg [(size_t)MAX_NODES * HDIM];
__device__ __half g_aggh[(size_t)MAX_NODES * HDIM];
__device__ __half g_xh  [(size_t)MAX_NODES * HDIM];
__device__ __half g_eh  [(size_t)MAX_EDGES * HDIM];
__device__ __half g_W1h [HDIM * 384];   // edge W1^T [n][k] fp16
__device__ __half g_W2h [HDIM * HDIM];
__device__ __half g_Wn1h[HDIM * 256];
__device__ __half g_Wn2h[HDIM * HDIM];

// ---------------- asm helpers ----------------
__device__ __forceinline__ void ldmat4(uint32_t r[4], uint32_t addr) {
    asm volatile("ldmatrix.sync.aligned.m8n8.x4.shared.b16 {%0,%1,%2,%3}, [%4];"
                 : "=r"(r[0]), "=r"(r[1]), "=r"(r[2]), "=r"(r[3]) : "r"(addr));
}
__device__ __forceinline__ void mma16816(float c[4], const uint32_t a[4],
                                         uint32_t b0, uint32_t b1) {
    asm volatile("mma.sync.aligned.m16n8k16.row.col.f32.f16.f16.f32 "
                 "{%0,%1,%2,%3},{%4,%5,%6,%7},{%8,%9},{%0,%1,%2,%3};"
                 : "+f"(c[0]), "+f"(c[1]), "+f"(c[2]), "+f"(c[3])
                 : "r"(a[0]), "r"(a[1]), "r"(a[2]), "r"(a[3]), "r"(b0), "r"(b1));
}
#define CP16(dst, src) \
    asm volatile("cp.async.ca.shared.global [%0], [%1], 16;" :: "r"(dst), "l"(src))
#define CPCOMMIT() asm volatile("cp.async.commit_group;")
#define CPWAIT1()  asm volatile("cp.async.wait_group 1;")
#define CPWAIT0()  asm volatile("cp.async.wait_group 0;")

// ---------------- smem layout (bytes) ----------------
// A0/A1, B0/B1, H0/H1: 128 rows x 64 halfs (128B rows, XOR-swizzled), 16KB each
#define AOFF 0
#define BOFF 32768
#define HOFF 65536
#define IDXO 98304
#define B1O  99328
#define B2O  99840
#define SMEM_BYTES 100352   // x2 CTAs = ~196KB/SM

// MODE 0: edge MLP (A = x[src]||x[dst]||eattr_h, K1=384, red-scatter to g_agg)
// MODE 1: node MLP (A = x||agg_h, K1=256, store to out)
template <int MODE, int K1>
__global__ __launch_bounds__(256, 2)
void gnn_h_kernel(const __half* __restrict__ xh,
                  const int* __restrict__ ei,
                  const __half* __restrict__ xtra,   // eattr_h (MODE0) / agg_h (MODE1)
                  const __half* __restrict__ W1h, const float* __restrict__ b1,
                  const __half* __restrict__ W2h, const float* __restrict__ b2,
                  float* __restrict__ out, int nrows, int E)
{
    extern __shared__ char smem[];
    const uint32_t su = (uint32_t)__cvta_generic_to_shared(smem);
    const int tid = threadIdx.x, lane = tid & 31, wid = tid >> 5;
    const int wm = wid >> 1, wn = wid & 1;
    const int base = blockIdx.x * 128;

    int*   sidx = (int*)(smem + IDXO);
    float* b1s  = (float*)(smem + B1O);
    float* b2s  = (float*)(smem + B2O);

    if (tid < 128) {
        b1s[tid] = b1[tid];
        b2s[tid] = b2[tid];
        if (MODE == 0) {
            int e = base + tid; if (e >= nrows) e = nrows - 1;
            sidx[tid]       = ei[e];
            sidx[128 + tid] = ei[E + e];
        }
    }
    __syncthreads();

    // loader coords: row r (0..127), half h (0/1 -> 64B of the 128B row)
    const int r = tid >> 1, h = tid & 1;
    int lr = base + r; if (lr >= nrows) lr = nrows - 1;
    const __half* asrc[3];
    if (MODE == 0) {
        asrc[0] = xh + (size_t)sidx[r] * HDIM;
        asrc[1] = xh + (size_t)sidx[128 + r] * HDIM;
        asrc[2] = xtra + (size_t)lr * HDIM;
    } else {
        asrc[0] = xh + (size_t)lr * HDIM;
        asrc[1] = xtra + (size_t)lr * HDIM;
        asrc[2] = nullptr;
    }

    const int NCH1 = K1 / 64;
    const int NTOT = NCH1 + 2;
    const int rsw = r & 7;

    // ---- prefetch ----
    auto prefetch = [&](int c) {
        {   // B chunk (weights, fp16, pre-transposed [n][k])
            const __half* W; int Ks, ko;
            if (c < NCH1) { W = W1h; Ks = K1; ko = c * 64; }
            else          { W = W2h; Ks = HDIM; ko = (c - NCH1) * 64; }
            const char* s = (const char*)(W + (size_t)r * Ks + ko) + h * 64;
            uint32_t d = su + BOFF + (c & 1) * 16384 + r * 128;
            #pragma unroll
            for (int i = 0; i < 4; ++i)
                CP16(d + (((uint32_t)(h * 4 + i) ^ rsw) << 4), s + i * 16);
        }
        if (c < NCH1) {   // A chunk (all-fp16 gather)
            const char* s = (const char*)(asrc[c >> 1] + (c & 1) * 64) + h * 64;
            uint32_t d = su + AOFF + (c & 1) * 16384 + r * 128;
            #pragma unroll
            for (int i = 0; i < 4; ++i)
                CP16(d + (((uint32_t)(h * 4 + i) ^ rsw) << 4), s + i * 16);
        }
    };

    // ---- mma fragment addressing ----
    uint32_t aoff[2], asw[2];
    {
        int ra = wm * 32 + (lane & 15);
        aoff[0] = ra * 128;        asw[0] = ra & 7;
        aoff[1] = (ra + 16) * 128; asw[1] = (ra + 16) & 7;
    }
    const uint32_t aub = lane >> 4;
    uint32_t boff[4], bsw[4];
    {
        int nb0 = wn * 64 + ((lane >> 4) << 3) + (lane & 7);
        #pragma unroll
        for (int p = 0; p < 4; ++p) {
            int nb = nb0 + p * 16;
            boff[p] = nb * 128; bsw[p] = nb & 7;
        }
    }
    const uint32_t bub = (lane >> 3) & 1;

    // accumulators, bias-init (b1)
    const int mrow = wm * 32 + (lane >> 2);
    const int ncol = wn * 64 + (lane & 3) * 2;
    float acc[2][8][4];
    #pragma unroll
    for (int mt = 0; mt < 2; ++mt)
        #pragma unroll
        for (int nt = 0; nt < 8; ++nt) {
            int n = ncol + nt * 8;
            acc[mt][nt][0] = b1s[n]; acc[mt][nt][1] = b1s[n + 1];
            acc[mt][nt][2] = b1s[n]; acc[mt][nt][3] = b1s[n + 1];
        }

    prefetch(0); CPCOMMIT();

    #pragma unroll 1
    for (int c = 0; c < NTOT; ++c) {
        if (c + 1 < NTOT) { prefetch(c + 1); CPCOMMIT(); CPWAIT1(); }
        else              { CPWAIT0(); }
        __syncthreads();

        if (c == NCH1) {
            // hidden: ReLU -> fp16 -> H slabs (slab = wn), then re-init acc (b2)
            #pragma unroll
            for (int mt = 0; mt < 2; ++mt)
                #pragma unroll
                for (int nt = 0; nt < 8; ++nt) {
                    int m = mrow + mt * 16;
                    int n = ncol + nt * 8;
                    int k = n & 63;
                    uint32_t u = (uint32_t)k >> 3;
                    uint32_t bo = (uint32_t)(lane & 3) * 4;
                    __half2 lo = __floats2half2_rn(fmaxf(acc[mt][nt][0], 0.f),
                                                   fmaxf(acc[mt][nt][1], 0.f));
                    __half2 hi = __floats2half2_rn(fmaxf(acc[mt][nt][2], 0.f),
                                                   fmaxf(acc[mt][nt][3], 0.f));
                    char* s0 = smem + HOFF + wn * 16384 + m * 128
                             + ((u ^ (uint32_t)(m & 7)) << 4) + bo;
                    char* s1 = smem + HOFF + wn * 16384 + (m + 8) * 128
                             + ((u ^ (uint32_t)((m + 8) & 7)) << 4) + bo;
                    *(__half2*)s0 = lo;
                    *(__half2*)s1 = hi;
                    acc[mt][nt][0] = b2s[n]; acc[mt][nt][1] = b2s[n + 1];
                    acc[mt][nt][2] = b2s[n]; acc[mt][nt][3] = b2s[n + 1];
                }
            __syncthreads();
        }

        // ---- mma on chunk c ----
        const uint32_t Ab = (c < NCH1) ? (su + AOFF + (c & 1) * 16384)
                                       : (su + HOFF + (c - NCH1) * 16384);
        const uint32_t Bb = su + BOFF + (c & 1) * 16384;
        #pragma unroll
        for (int ks = 0; ks < 4; ++ks) {
            const uint32_t ua = aub + ks * 2;
            const uint32_t ub = bub + ks * 2;
            uint32_t a0[4], a1[4], bf[4][4];
            ldmat4(a0, Ab + aoff[0] + ((ua ^ asw[0]) << 4));
            ldmat4(a1, Ab + aoff[1] + ((ua ^ asw[1]) << 4));
            #pragma unroll
            for (int p = 0; p < 4; ++p)
                ldmat4(bf[p], Bb + boff[p] + ((ub ^ bsw[p]) << 4));
            #pragma unroll
            for (int nt = 0; nt < 8; ++nt) {
                mma16816(acc[0][nt], a0, bf[nt >> 1][(nt & 1) * 2], bf[nt >> 1][(nt & 1) * 2 + 1]);
                mma16816(acc[1][nt], a1, bf[nt >> 1][(nt & 1) * 2], bf[nt >> 1][(nt & 1) * 2 + 1]);
            }
        }
        __syncthreads();
    }

    // ---- epilogue: stage fp32, then scatter/store ----
    float* stg = (float*)smem;   // [128][132]
    #pragma unroll
    for (int mt = 0; mt < 2; ++mt)
        #pragma unroll
        for (int nt = 0; nt < 8; ++nt) {
            int m = mrow + mt * 16;
            int n = ncol + nt * 8;
            *(float2*)(stg + m * 132 + n)       = make_float2(acc[mt][nt][0], acc[mt][nt][1]);
            *(float2*)(stg + (m + 8) * 132 + n) = make_float2(acc[mt][nt][2], acc[mt][nt][3]);
        }
    __syncthreads();

    {
        const int row = tid >> 1, hh = tid & 1;
        if (base + row < nrows) {
            const float* s = stg + row * 132 + hh * 64;
            if (MODE == 0) {
                const int cd = sidx[128 + row];
                float* dst = g_agg + (size_t)cd * HDIM + hh * 64;
                #pragma unroll
                for (int i = 0; i < 16; ++i) {
                    float4 v = ((const float4*)s)[i];
                    asm volatile("red.global.add.v4.f32 [%0], {%1,%2,%3,%4};"
                                 :: "l"(dst + i * 4), "f"(v.x), "f"(v.y),
                                    "f"(v.z), "f"(v.w) : "memory");
                }
            } else {
                float4* dst = (float4*)(out + (size_t)(base + row) * HDIM + hh * 64);
                #pragma unroll
                for (int i = 0; i < 16; ++i)
                    dst[i] = ((const float4*)s)[i];
            }
        }
    }
}

// weight prep: dst[n*K+k] = half(src[k*128+n])
__global__ void prep_w_h(__half* dst, const float* src, int K) {
    int i = blockIdx.x * 256 + threadIdx.x;
    if (i < K * HDIM) {
        int k = i / HDIM, n = i % HDIM;
        dst[(size_t)n * K + k] = __float2half(src[(size_t)k * HDIM + n]);
    }
}
// bulk fp32 -> fp16, 8 elems/thread, vectorized
__global__ void conv_h8(__half* __restrict__ dst, const float* __restrict__ src,
                        size_t n8) {
    size_t i = (size_t)blockIdx.x * 256 + threadIdx.x;
    if (i < n8) {
        float4 v0 = ((const float4*)src)[i * 2];
        float4 v1 = ((const float4*)src)[i * 2 + 1];
        __half2 h[4] = { __floats2half2_rn(v0.x, v0.y), __floats2half2_rn(v0.z, v0.w),
                         __floats2half2_rn(v1.x, v1.y), __floats2half2_rn(v1.z, v1.w) };
        *(uint4*)(dst + i * 8) = *(const uint4*)h;
    }
}

extern "C" void kernel_launch(void* const* d_in, const int* in_sizes, int n_in,
                              void* d_out, int out_size)
{
    const float* x     = (const float*)d_in[0];
    const int*   ei    = (const int*)d_in[1];
    const float* eattr = (const float*)d_in[2];
    const float* We1   = (const float*)d_in[3];
    const float* be1   = (const float*)d_in[4];
    const float* We2   = (const float*)d_in[5];
    const float* be2   = (const float*)d_in[6];
    const float* Wn1   = (const float*)d_in[7];
    const float* bn1   = (const float*)d_in[8];
    const float* Wn2   = (const float*)d_in[9];
    const float* bn2   = (const float*)d_in[10];
    float* out = (float*)d_out;

    const int N = in_sizes[0] / HDIM;   // 50000
    const int E = in_sizes[1] / 2;      // 800000

    cudaFuncSetAttribute(gnn_h_kernel<0, 384>,
                         cudaFuncAttributeMaxDynamicSharedMemorySize, SMEM_BYTES);
    cudaFuncSetAttribute(gnn_h_kernel<1, 256>,
                         cudaFuncAttributeMaxDynamicSharedMemorySize, SMEM_BYTES);

    void *aggp, *agghp, *xhp, *ehp, *w1, *w2, *wn1, *wn2;
    cudaGetSymbolAddress(&aggp,  g_agg);
    cudaGetSymbolAddress(&agghp, g_aggh);
    cudaGetSymbolAddress(&xhp,   g_xh);
    cudaGetSymbolAddress(&ehp,   g_eh);
    cudaGetSymbolAddress(&w1,    g_W1h);
    cudaGetSymbolAddress(&w2,    g_W2h);
    cudaGetSymbolAddress(&wn1,   g_Wn1h);
    cudaGetSymbolAddress(&wn2,   g_Wn2h);

    cudaMemsetAsync(aggp, 0, (size_t)N * HDIM * sizeof(float), 0);
    prep_w_h<<<(384 * HDIM + 255) / 256, 256>>>((__half*)w1,  We1, 384);
    prep_w_h<<<(HDIM * HDIM + 255) / 256, 256>>>((__half*)w2,  We2, HDIM);
    prep_w_h<<<(256 * HDIM + 255) / 256, 256>>>((__half*)wn1, Wn1, 256);
    prep_w_h<<<(HDIM * HDIM + 255) / 256, 256>>>((__half*)wn2, Wn2, HDIM);

    const size_t nx8 = (size_t)N * HDIM / 8;
    const size_t ne8 = (size_t)E * HDIM / 8;
    conv_h8<<<(unsigned)((nx8 + 255) / 256), 256>>>((__half*)xhp, x, nx8);
    conv_h8<<<(unsigned)((ne8 + 255) / 256), 256>>>((__half*)ehp, eattr, ne8);

    gnn_h_kernel<0, 384><<<(E + 127) / 128, 256, SMEM_BYTES>>>(
        (const __half*)xhp, ei, (const __half*)ehp,
        (const __half*)w1, be1, (const __half*)w2, be2, nullptr, E, E);

    conv_h8<<<(unsigned)((nx8 + 255) / 256), 256>>>((__half*)agghp,
                                                    (const float*)aggp, nx8);

    gnn_h_kernel<1, 256><<<(N + 127) / 128, 256, SMEM_BYTES>>>(
        (const __half*)xhp, nullptr, (const __half*)agghp,
        (const __half*)wn1, bn1, (const __half*)wn2, bn2, out, N, 0);
}

// round 7
// speedup vs baseline: 4.5675x; 1.0052x over previous
#include <cuda_runtime.h>
#include <cuda_fp16.h>
#include <cstdint>

#define HDIM 128
#define MAX_NODES 50000
#define MAX_EDGES 800000

// ---------------- device scratch ----------------
__device__ float  g_agg [(size_t)MAX_NODES * HDIM];
__device__ __half g_aggh[(size_t)MAX_NODES * HDIM];
__device__ __half g_xh  [(size_t)MAX_NODES * HDIM];
__device__ __half g_eh  [(size_t)MAX_EDGES * HDIM];
__device__ __half g_W1h [HDIM * 384];   // edge W1^T [n][k] fp16
__device__ __half g_W2h [HDIM * HDIM];
__device__ __half g_Wn1h[HDIM * 256];
__device__ __half g_Wn2h[HDIM * HDIM];

// ---------------- asm helpers ----------------
__device__ __forceinline__ void ldmat4(uint32_t r[4], uint32_t addr) {
    asm volatile("ldmatrix.sync.aligned.m8n8.x4.shared.b16 {%0,%1,%2,%3}, [%4];"
                 : "=r"(r[0]), "=r"(r[1]), "=r"(r[2]), "=r"(r[3]) : "r"(addr));
}
__device__ __forceinline__ void mma16816(float c[4], const uint32_t a[4],
                                         uint32_t b0, uint32_t b1) {
    asm volatile("mma.sync.aligned.m16n8k16.row.col.f32.f16.f16.f32 "
                 "{%0,%1,%2,%3},{%4,%5,%6,%7},{%8,%9},{%0,%1,%2,%3};"
                 : "+f"(c[0]), "+f"(c[1]), "+f"(c[2]), "+f"(c[3])
                 : "r"(a[0]), "r"(a[1]), "r"(a[2]), "r"(a[3]), "r"(b0), "r"(b1));
}
#define CP16(dst, src) \
    asm volatile("cp.async.ca.shared.global [%0], [%1], 16;" :: "r"(dst), "l"(src))
#define CPCOMMIT() asm volatile("cp.async.commit_group;")
#define CPWAIT0()  asm volatile("cp.async.wait_group 0;")

// ---------------- smem layout (bytes) ----------------
// A0/A1, B0/B1, H0/H1: 128 rows x 64 halfs (128B rows, XOR-swizzled), 16KB each
#define AOFF 0
#define BOFF 32768
#define HOFF 65536
#define IDXO 98304
#define B1O  99328
#define B2O  99840
#define SMEM_BYTES 100352   // x2 CTAs = ~196KB/SM

// MODE 0: edge MLP (A = x[src]||x[dst]||eattr_h, K1=384, red-scatter to g_agg)
// MODE 1: node MLP (A = x||agg_h, K1=256, store to out)
template <int MODE, int K1>
__global__ __launch_bounds__(256, 2)
void gnn_h_kernel(const __half* __restrict__ xh,
                  const int* __restrict__ ei,
                  const __half* __restrict__ xtra,   // eattr_h (MODE0) / agg_h (MODE1)
                  const __half* __restrict__ W1h, const float* __restrict__ b1,
                  const __half* __restrict__ W2h, const float* __restrict__ b2,
                  float* __restrict__ out, int nrows, int E)
{
    extern __shared__ char smem[];
    const uint32_t su = (uint32_t)__cvta_generic_to_shared(smem);
    const int tid = threadIdx.x, lane = tid & 31, wid = tid >> 5;
    const int wm = wid >> 1, wn = wid & 1;
    const int base = blockIdx.x * 128;

    int*   sidx = (int*)(smem + IDXO);
    float* b1s  = (float*)(smem + B1O);
    float* b2s  = (float*)(smem + B2O);

    if (tid < 128) {
        b1s[tid] = b1[tid];
        b2s[tid] = b2[tid];
        if (MODE == 0) {
            int e = base + tid; if (e >= nrows) e = nrows - 1;
            sidx[tid]       = ei[e];
            sidx[128 + tid] = ei[E + e];
        }
    }
    __syncthreads();

    // loader coords: row r (0..127), half h (0/1 -> 64B of the 128B row)
    const int r = tid >> 1, h = tid & 1;
    int lr = base + r; if (lr >= nrows) lr = nrows - 1;
    const __half* asrc[3];
    if (MODE == 0) {
        asrc[0] = xh + (size_t)sidx[r] * HDIM;
        asrc[1] = xh + (size_t)sidx[128 + r] * HDIM;
        asrc[2] = xtra + (size_t)lr * HDIM;
    } else {
        asrc[0] = xh + (size_t)lr * HDIM;
        asrc[1] = xtra + (size_t)lr * HDIM;
        asrc[2] = nullptr;
    }

    const int NCH1 = K1 / 64;
    const int NTOT = NCH1 + 2;
    const int rsw = r & 7;

    // ---- prefetch ----
    auto prefetch = [&](int c) {
        {   // B chunk (weights, fp16, pre-transposed [n][k])
            const __half* W; int Ks, ko;
            if (c < NCH1) { W = W1h; Ks = K1; ko = c * 64; }
            else          { W = W2h; Ks = HDIM; ko = (c - NCH1) * 64; }
            const char* s = (const char*)(W + (size_t)r * Ks + ko) + h * 64;
            uint32_t d = su + BOFF + (c & 1) * 16384 + r * 128;
            #pragma unroll
            for (int i = 0; i < 4; ++i)
                CP16(d + (((uint32_t)(h * 4 + i) ^ rsw) << 4), s + i * 16);
        }
        if (c < NCH1) {   // A chunk (all-fp16 gather)
            const char* s = (const char*)(asrc[c >> 1] + (c & 1) * 64) + h * 64;
            uint32_t d = su + AOFF + (c & 1) * 16384 + r * 128;
            #pragma unroll
            for (int i = 0; i < 4; ++i)
                CP16(d + (((uint32_t)(h * 4 + i) ^ rsw) << 4), s + i * 16);
        }
    };

    // ---- mma fragment addressing ----
    uint32_t aoff[2], asw[2];
    {
        int ra = wm * 32 + (lane & 15);
        aoff[0] = ra * 128;        asw[0] = ra & 7;
        aoff[1] = (ra + 16) * 128; asw[1] = (ra + 16) & 7;
    }
    const uint32_t aub = lane >> 4;
    uint32_t boff[4], bsw[4];
    {
        int nb0 = wn * 64 + ((lane >> 4) << 3) + (lane & 7);
        #pragma unroll
        for (int p = 0; p < 4; ++p) {
            int nb = nb0 + p * 16;
            boff[p] = nb * 128; bsw[p] = nb & 7;
        }
    }
    const uint32_t bub = (lane >> 3) & 1;

    // accumulators, bias-init (b1)
    const int mrow = wm * 32 + (lane >> 2);
    const int ncol = wn * 64 + (lane & 3) * 2;
    float acc[2][8][4];
    #pragma unroll
    for (int mt = 0; mt < 2; ++mt)
        #pragma unroll
        for (int nt = 0; nt < 8; ++nt) {
            int n = ncol + nt * 8;
            acc[mt][nt][0] = b1s[n]; acc[mt][nt][1] = b1s[n + 1];
            acc[mt][nt][2] = b1s[n]; acc[mt][nt][3] = b1s[n + 1];
        }

    prefetch(0); CPCOMMIT();

    // ---- mainloop: ONE barrier per iteration ----
    // order: wait(c) -> sync -> prefetch(c+1) -> [hidden transition] -> mma(c)
    // prefetch(c+1) writes buffer (c+1)&1; all warps passed the barrier, i.e.
    // finished mma(c-1) which was the last reader of that buffer.
    #pragma unroll 1
    for (int c = 0; c < NTOT; ++c) {
        CPWAIT0();
        __syncthreads();
        if (c + 1 < NTOT) { prefetch(c + 1); CPCOMMIT(); }

        if (c == NCH1) {
            // hidden: ReLU -> fp16 -> H slabs (slab = wn), then re-init acc (b2)
            #pragma unroll
            for (int mt = 0; mt < 2; ++mt)
                #pragma unroll
                for (int nt = 0; nt < 8; ++nt) {
                    int m = mrow + mt * 16;
                    int n = ncol + nt * 8;
                    int k = n & 63;
                    uint32_t u = (uint32_t)k >> 3;
                    uint32_t bo = (uint32_t)(lane & 3) * 4;
                    __half2 lo = __floats2half2_rn(fmaxf(acc[mt][nt][0], 0.f),
                                                   fmaxf(acc[mt][nt][1], 0.f));
                    __half2 hi = __floats2half2_rn(fmaxf(acc[mt][nt][2], 0.f),
                                                   fmaxf(acc[mt][nt][3], 0.f));
                    char* s0 = smem + HOFF + wn * 16384 + m * 128
                             + ((u ^ (uint32_t)(m & 7)) << 4) + bo;
                    char* s1 = smem + HOFF + wn * 16384 + (m + 8) * 128
                             + ((u ^ (uint32_t)((m + 8) & 7)) << 4) + bo;
                    *(__half2*)s0 = lo;
                    *(__half2*)s1 = hi;
                    acc[mt][nt][0] = b2s[n]; acc[mt][nt][1] = b2s[n + 1];
                    acc[mt][nt][2] = b2s[n]; acc[mt][nt][3] = b2s[n + 1];
                }
            __syncthreads();
        }

        // ---- mma on chunk c ----
        const uint32_t Ab = (c < NCH1) ? (su + AOFF + (c & 1) * 16384)
                                       : (su + HOFF + (c - NCH1) * 16384);
        const uint32_t Bb = su + BOFF + (c & 1) * 16384;
        #pragma unroll
        for (int ks = 0; ks < 4; ++ks) {
            const uint32_t ua = aub + ks * 2;
            const uint32_t ub = bub + ks * 2;
            uint32_t a0[4], a1[4], bf[4][4];
            ldmat4(a0, Ab + aoff[0] + ((ua ^ asw[0]) << 4));
            ldmat4(a1, Ab + aoff[1] + ((ua ^ asw[1]) << 4));
            #pragma unroll
            for (int p = 0; p < 4; ++p)
                ldmat4(bf[p], Bb + boff[p] + ((ub ^ bsw[p]) << 4));
            #pragma unroll
            for (int nt = 0; nt < 8; ++nt) {
                mma16816(acc[0][nt], a0, bf[nt >> 1][(nt & 1) * 2], bf[nt >> 1][(nt & 1) * 2 + 1]);
                mma16816(acc[1][nt], a1, bf[nt >> 1][(nt & 1) * 2], bf[nt >> 1][(nt & 1) * 2 + 1]);
            }
        }
    }
    __syncthreads();   // last mma done everywhere before staging overwrites A/B

    // ---- epilogue: stage fp32, then scatter/store ----
    float* stg = (float*)smem;   // [128][132]
    #pragma unroll
    for (int mt = 0; mt < 2; ++mt)
        #pragma unroll
        for (int nt = 0; nt < 8; ++nt) {
            int m = mrow + mt * 16;
            int n = ncol + nt * 8;
            *(float2*)(stg + m * 132 + n)       = make_float2(acc[mt][nt][0], acc[mt][nt][1]);
            *(float2*)(stg + (m + 8) * 132 + n) = make_float2(acc[mt][nt][2], acc[mt][nt][3]);
        }
    __syncthreads();

    {
        const int row = tid >> 1, hh = tid & 1;
        if (base + row < nrows) {
            const float* s = stg + row * 132 + hh * 64;
            if (MODE == 0) {
                const int cd = sidx[128 + row];
                float* dst = g_agg + (size_t)cd * HDIM + hh * 64;
                #pragma unroll
                for (int i = 0; i < 16; ++i) {
                    float4 v = ((const float4*)s)[i];
                    asm volatile("red.global.add.v4.f32 [%0], {%1,%2,%3,%4};"
                                 :: "l"(dst + i * 4), "f"(v.x), "f"(v.y),
                                    "f"(v.z), "f"(v.w) : "memory");
                }
            } else {
                float4* dst = (float4*)(out + (size_t)(base + row) * HDIM + hh * 64);
                #pragma unroll
                for (int i = 0; i < 16; ++i)
                    dst[i] = ((const float4*)s)[i];
            }
        }
    }
}

// weight prep: dst[n*K+k] = half(src[k*128+n])
__global__ void prep_w_h(__half* dst, const float* src, int K) {
    int i = blockIdx.x * 256 + threadIdx.x;
    if (i < K * HDIM) {
        int k = i / HDIM, n = i % HDIM;
        dst[(size_t)n * K + k] = __float2half(src[(size_t)k * HDIM + n]);
    }
}
// fused fp32->fp16 for two buffers (x then eattr), 8 elems/thread
__global__ void conv_h8_2(__half* __restrict__ d0, const float* __restrict__ s0,
                          size_t n8_0,
                          __half* __restrict__ d1, const float* __restrict__ s1,
                          size_t n8_1) {
    size_t i = (size_t)blockIdx.x * 256 + threadIdx.x;
    const float* src; __half* dst; size_t j;
    if (i < n8_0)            { src = s0; dst = d0; j = i; }
    else if (i < n8_0 + n8_1){ src = s1; dst = d1; j = i - n8_0; }
    else return;
    float4 v0 = ((const float4*)src)[j * 2];
    float4 v1 = ((const float4*)src)[j * 2 + 1];
    __half2 hh[4] = { __floats2half2_rn(v0.x, v0.y), __floats2half2_rn(v0.z, v0.w),
                      __floats2half2_rn(v1.x, v1.y), __floats2half2_rn(v1.z, v1.w) };
    *(uint4*)(dst + j * 8) = *(const uint4*)hh;
}
// fp32 -> fp16, 8 elems/thread (agg conversion between the two main launches)
__global__ void conv_h8(__half* __restrict__ dst, const float* __restrict__ src,
                        size_t n8) {
    size_t i = (size_t)blockIdx.x * 256 + threadIdx.x;
    if (i < n8) {
        float4 v0 = ((const float4*)src)[i * 2];
        float4 v1 = ((const float4*)src)[i * 2 + 1];
        __half2 hh[4] = { __floats2half2_rn(v0.x, v0.y), __floats2half2_rn(v0.z, v0.w),
                          __floats2half2_rn(v1.x, v1.y), __floats2half2_rn(v1.z, v1.w) };
        *(uint4*)(dst + i * 8) = *(const uint4*)hh;
    }
}

extern "C" void kernel_launch(void* const* d_in, const int* in_sizes, int n_in,
                              void* d_out, int out_size)
{
    const float* x     = (const float*)d_in[0];
    const int*   ei    = (const int*)d_in[1];
    const float* eattr = (const float*)d_in[2];
    const float* We1   = (const float*)d_in[3];
    const float* be1   = (const float*)d_in[4];
    const float* We2   = (const float*)d_in[5];
    const float* be2   = (const float*)d_in[6];
    const float* Wn1   = (const float*)d_in[7];
    const float* bn1   = (const float*)d_in[8];
    const float* Wn2   = (const float*)d_in[9];
    const float* bn2   = (const float*)d_in[10];
    float* out = (float*)d_out;

    const int N = in_sizes[0] / HDIM;   // 50000
    const int E = in_sizes[1] / 2;      // 800000

    cudaFuncSetAttribute(gnn_h_kernel<0, 384>,
                         cudaFuncAttributeMaxDynamicSharedMemorySize, SMEM_BYTES);
    cudaFuncSetAttribute(gnn_h_kernel<1, 256>,
                         cudaFuncAttributeMaxDynamicSharedMemorySize, SMEM_BYTES);

    void *aggp, *agghp, *xhp, *ehp, *w1, *w2, *wn1, *wn2;
    cudaGetSymbolAddress(&aggp,  g_agg);
    cudaGetSymbolAddress(&agghp, g_aggh);
    cudaGetSymbolAddress(&xhp,   g_xh);
    cudaGetSymbolAddress(&ehp,   g_eh);
    cudaGetSymbolAddress(&w1,    g_W1h);
    cudaGetSymbolAddress(&w2,    g_W2h);
    cudaGetSymbolAddress(&wn1,   g_Wn1h);
    cudaGetSymbolAddress(&wn2,   g_Wn2h);

    cudaMemsetAsync(aggp, 0, (size_t)N * HDIM * sizeof(float), 0);

    // exactly 5 kernel launches before the edge kernel (ncu -s 5 profiles it)
    prep_w_h<<<(384 * HDIM + 255) / 256, 256>>>((__half*)w1,  We1, 384);
    prep_w_h<<<(HDIM * HDIM + 255) / 256, 256>>>((__half*)w2,  We2, HDIM);
    prep_w_h<<<(256 * HDIM + 255) / 256, 256>>>((__half*)wn1, Wn1, 256);
    prep_w_h<<<(HDIM * HDIM + 255) / 256, 256>>>((__half*)wn2, Wn2, HDIM);

    const size_t nx8 = (size_t)N * HDIM / 8;
    const size_t ne8 = (size_t)E * HDIM / 8;
    conv_h8_2<<<(unsigned)((nx8 + ne8 + 255) / 256), 256>>>(
        (__half*)xhp, x, nx8, (__half*)ehp, eattr, ne8);

    gnn_h_kernel<0, 384><<<(E + 127) / 128, 256, SMEM_BYTES>>>(
        (const __half*)xhp, ei, (const __half*)ehp,
        (const __half*)w1, be1, (const __half*)w2, be2, nullptr, E, E);

    conv_h8<<<(unsigned)((nx8 + 255) / 256), 256>>>((__half*)agghp,
                                                    (const float*)aggp, nx8);

    gnn_h_kernel<1, 256><<<(N + 127) / 128, 256, SMEM_BYTES>>>(
        (const __half*)xhp, nullptr, (const __half*)agghp,
        (const __half*)wn1, bn1, (const __half*)wn2, bn2, out, N, 0);
}